// round 2
// baseline (speedup 1.0000x reference)
#include <cuda_runtime.h>
#include <cuda_bf16.h>
#include <cstdint>

// Problem constants (match reference)
#define NPTS 200000
#define BATCH 4
#define CV 64
#define CI 256
#define HF 48
#define WF 160
#define HW (HF * WF)          // 7680
#define OUTW (CV + CI)        // 320

// Scratch: img_feats transposed to [B, H, W, C] (channels contiguous).
// 4 * 7680 * 256 floats = 31.4 MB — L2-resident (L2 is ~126 MB).
__device__ float g_imgT[(size_t)BATCH * HW * CI];

// ---------------------------------------------------------------------------
// Kernel A: [B, C, H*W] -> [B, H*W, C] tiled transpose (coalesced both ways)
// grid: (HW/32, CI/32, B), block: (32, 8)
// ---------------------------------------------------------------------------
__global__ void transpose_kernel(const float* __restrict__ img) {
    __shared__ float tile[32][33];
    const int b  = blockIdx.z;
    const int p0 = blockIdx.x * 32;   // position tile (h*W + w)
    const int c0 = blockIdx.y * 32;   // channel tile

    const float* src = img    + (size_t)b * CI * HW;
    float*       dst = g_imgT + (size_t)b * HW * CI;

    #pragma unroll
    for (int i = threadIdx.y; i < 32; i += 8)
        tile[i][threadIdx.x] = src[(size_t)(c0 + i) * HW + (p0 + threadIdx.x)];
    __syncthreads();
    #pragma unroll
    for (int i = threadIdx.y; i < 32; i += 8)
        dst[(size_t)(p0 + i) * CI + (c0 + threadIdx.x)] = tile[threadIdx.x][i];
}

// corner accumulate helper (no macro — avoids token collision with .w member)
__device__ __forceinline__ void corner_acc(const float* __restrict__ base,
                                           int yi, int xi, float w, int coff,
                                           float4& a0, float4& a1) {
    if (w != 0.0f) {
        const float4* p = (const float4*)(base + ((size_t)yi * WF + xi) * CI + coff);
        float4 v0 = p[0], v1 = p[1];
        a0.x += w * v0.x; a0.y += w * v0.y; a0.z += w * v0.z; a0.w += w * v0.w;
        a1.x += w * v1.x; a1.y += w * v1.y; a1.z += w * v1.z; a1.w += w * v1.w;
    }
}

// ---------------------------------------------------------------------------
// Kernel B: one warp per point.
// Each lane owns 8 channels (2 x float4). 4 weighted corner gathers from the
// transposed (channel-contiguous) feature map; zero-weight corners skipped
// (warp-uniform branch). Row write fully coalesced.
// ---------------------------------------------------------------------------
__global__ __launch_bounds__(256)
void sample_kernel(const float* __restrict__ points_mean,
                   const float* __restrict__ voxel_feats,
                   const int*   __restrict__ coors,
                   const float* __restrict__ lidar2img,
                   const int*   __restrict__ pad_shape,
                   float*       __restrict__ out) {
    const int gwarp = (blockIdx.x * blockDim.x + threadIdx.x) >> 5;
    const int lane  = threadIdx.x & 31;
    if (gwarp >= NPTS) return;
    const int n = gwarp;

    const int b = __ldg(&coors[(size_t)n * 4]);

    const float px = __ldg(&points_mean[(size_t)n * 3 + 0]);
    const float py = __ldg(&points_mean[(size_t)n * 3 + 1]);
    const float pz = __ldg(&points_mean[(size_t)n * 3 + 2]);

    const float* M = lidar2img + (size_t)b * 16;
    const float p0 = __ldg(&M[0]) * px + __ldg(&M[1]) * py + __ldg(&M[2])  * pz + __ldg(&M[3]);
    const float p1 = __ldg(&M[4]) * px + __ldg(&M[5]) * py + __ldg(&M[6])  * pz + __ldg(&M[7]);
    const float p2 = __ldg(&M[8]) * px + __ldg(&M[9]) * py + __ldg(&M[10]) * pz + __ldg(&M[11]);

    const float z     = fmaxf(p2, 1e-5f);
    const float x_pix = p0 / z;
    const float y_pix = p1 / z;

    const float padH = (float)__ldg(&pad_shape[(size_t)b * 2 + 0]);
    const float padW = (float)__ldg(&pad_shape[(size_t)b * 2 + 1]);

    const float gx = x_pix / padW * 2.0f - 1.0f;
    const float gy = y_pix / padH * 2.0f - 1.0f;
    const float ix = (gx + 1.0f) * 0.5f * (float)(WF - 1);
    const float iy = (gy + 1.0f) * 0.5f * (float)(HF - 1);

    const float ix0f = floorf(ix);
    const float iy0f = floorf(iy);
    const float wx1 = ix - ix0f, wx0 = 1.0f - wx1;
    const float wy1 = iy - iy0f, wy0 = 1.0f - wy1;

    const int ix0 = (int)ix0f, iy0 = (int)iy0f;
    const int ix1 = ix0 + 1,   iy1 = iy0 + 1;

    const bool vx0 = (ix0 >= 0) & (ix0 < WF);
    const bool vx1 = (ix1 >= 0) & (ix1 < WF);
    const bool vy0 = (iy0 >= 0) & (iy0 < HF);
    const bool vy1 = (iy1 >= 0) & (iy1 < HF);

    const float w00 = (vy0 & vx0) ? (wy0 * wx0) : 0.0f;
    const float w01 = (vy0 & vx1) ? (wy0 * wx1) : 0.0f;
    const float w10 = (vy1 & vx0) ? (wy1 * wx0) : 0.0f;
    const float w11 = (vy1 & vx1) ? (wy1 * wx1) : 0.0f;

    float4 a0 = make_float4(0.f, 0.f, 0.f, 0.f);
    float4 a1 = make_float4(0.f, 0.f, 0.f, 0.f);

    const float* base = g_imgT + (size_t)b * HW * CI;
    const int coff = lane * 8;  // this lane's channel offset

    corner_acc(base, iy0, ix0, w00, coff, a0, a1);
    corner_acc(base, iy0, ix1, w01, coff, a0, a1);
    corner_acc(base, iy1, ix0, w10, coff, a0, a1);
    corner_acc(base, iy1, ix1, w11, coff, a0, a1);

    // Output row: [64 voxel | 256 point] floats = 80 float4, 16B aligned.
    float4* orow = (float4*)(out + (size_t)n * OUTW);

    // voxel copy: 16 float4 by lanes 0..15
    if (lane < 16) {
        const float4* vrow = (const float4*)(voxel_feats + (size_t)n * CV);
        orow[lane] = __ldg(&vrow[lane]);
    }

    // point feats: 64 float4, 2 per lane, coalesced
    orow[16 + lane * 2 + 0] = a0;
    orow[16 + lane * 2 + 1] = a1;
}

// ---------------------------------------------------------------------------
extern "C" void kernel_launch(void* const* d_in, const int* in_sizes, int n_in,
                              void* d_out, int out_size) {
    const float* points_mean = (const float*)d_in[0];
    // d_in[1] = mask (unused by reference)
    const float* voxel_feats = (const float*)d_in[2];
    const int*   coors       = (const int*)  d_in[3];
    const float* img_feats   = (const float*)d_in[4];
    const float* lidar2img   = (const float*)d_in[5];
    const int*   pad_shape   = (const int*)  d_in[6];
    float*       out         = (float*)d_out;

    // Kernel A: transpose img_feats -> [B, H*W, C]
    dim3 tgrid(HW / 32, CI / 32, BATCH);
    dim3 tblock(32, 8);
    transpose_kernel<<<tgrid, tblock>>>(img_feats);

    // Kernel B: one warp per point
    const int threads = 256;
    const int warps_per_block = threads / 32;
    const int blocks = (NPTS + warps_per_block - 1) / warps_per_block;
    sample_kernel<<<blocks, threads>>>(points_mean, voxel_feats, coors,
                                       lidar2img, pad_shape, out);
}

// round 3
// speedup vs baseline: 1.1076x; 1.1076x over previous
#include <cuda_runtime.h>
#include <cuda_bf16.h>
#include <cstdint>

// Problem constants (match reference)
#define NPTS 200000
#define BATCH 4
#define CV 64
#define CI 256
#define HF 48
#define WF 160
#define HW (HF * WF)          // 7680
#define OUTW (CV + CI)        // 320

// Scratch: img_feats transposed to [B, H, W, C] (channels contiguous).
// 4 * 7680 * 256 floats = 31.4 MB — L2-resident (L2 ~126 MB).
__device__ float g_imgT[(size_t)BATCH * HW * CI];

// ---------------------------------------------------------------------------
// Kernel A: [B, C, H*W] -> [B, H*W, C] transpose, float4 on BOTH global sides.
// Tile: 32 channels x 128 positions. Block: 256 threads. Grid: (60, 8, 4).
// smem padded [32][129] -> conflict-free strided reads in store phase.
// ---------------------------------------------------------------------------
__global__ __launch_bounds__(256)
void transpose_kernel(const float* __restrict__ img) {
    __shared__ float tile[32][129];
    const int b  = blockIdx.z;
    const int p0 = blockIdx.x * 128;  // position tile base
    const int c0 = blockIdx.y * 32;   // channel tile base
    const int t  = threadIdx.x;

    const float* src = img    + (size_t)b * CI * HW;
    float*       dst = g_imgT + (size_t)b * HW * CI;

    // Load: 32 channels x 32 float4 (128 positions) = 1024 float4, 4/thread.
    #pragma unroll
    for (int r = 0; r < 4; r++) {
        const int linear = r * 256 + t;       // 0..1023
        const int c = linear >> 5;            // 0..31
        const int q = linear & 31;            // position quad 0..31
        float4 v = *(const float4*)(src + (size_t)(c0 + c) * HW + p0 + q * 4);
        tile[c][q * 4 + 0] = v.x;
        tile[c][q * 4 + 1] = v.y;
        tile[c][q * 4 + 2] = v.z;
        tile[c][q * 4 + 3] = v.w;
    }
    __syncthreads();

    // Store: 128 positions x 8 float4 (32 channels) = 1024 float4, 4/thread.
    #pragma unroll
    for (int r = 0; r < 4; r++) {
        const int linear = r * 256 + t;       // 0..1023
        const int p  = linear >> 3;           // 0..127
        const int cq = linear & 7;            // channel quad 0..7
        float4 v;
        v.x = tile[cq * 4 + 0][p];
        v.y = tile[cq * 4 + 1][p];
        v.z = tile[cq * 4 + 2][p];
        v.w = tile[cq * 4 + 3][p];
        *(float4*)(dst + (size_t)(p0 + p) * CI + c0 + cq * 4) = v;
    }
}

// corner accumulate helper; off0/off1 are this lane's float offsets
__device__ __forceinline__ void corner_acc(const float* __restrict__ base,
                                           int yi, int xi, float w,
                                           int off0, int off1,
                                           float4& a0, float4& a1) {
    if (w != 0.0f) {
        const float* row = base + ((size_t)yi * WF + xi) * CI;
        float4 v0 = *(const float4*)(row + off0);
        float4 v1 = *(const float4*)(row + off1);
        a0.x += w * v0.x; a0.y += w * v0.y; a0.z += w * v0.z; a0.w += w * v0.w;
        a1.x += w * v1.x; a1.y += w * v1.y; a1.z += w * v1.z; a1.w += w * v1.w;
    }
}

// streaming store / load helpers
__device__ __forceinline__ void stcs4(float4* p, float4 v) {
#if __CUDA_ARCH__ >= 320
    __stcs(p, v);
#else
    *p = v;
#endif
}

// ---------------------------------------------------------------------------
// Kernel B: one warp per point.
// Lane owns channels [4*lane, 4*lane+4) and [128+4*lane, +4): every
// LDG.128 / STG.128 across the warp is a dense 512 B transaction.
// Zero-weight corners skipped (warp-uniform). Output written streaming
// (__stcs) to keep the transposed image L2-resident.
// ---------------------------------------------------------------------------
__global__ __launch_bounds__(256)
void sample_kernel(const float* __restrict__ points_mean,
                   const float* __restrict__ voxel_feats,
                   const int*   __restrict__ coors,
                   const float* __restrict__ lidar2img,
                   const int*   __restrict__ pad_shape,
                   float*       __restrict__ out) {
    const int gwarp = (blockIdx.x * blockDim.x + threadIdx.x) >> 5;
    const int lane  = threadIdx.x & 31;
    if (gwarp >= NPTS) return;
    const int n = gwarp;

    const int b = __ldg(&coors[(size_t)n * 4]);

    const float px = __ldg(&points_mean[(size_t)n * 3 + 0]);
    const float py = __ldg(&points_mean[(size_t)n * 3 + 1]);
    const float pz = __ldg(&points_mean[(size_t)n * 3 + 2]);

    const float* M = lidar2img + (size_t)b * 16;
    const float p0 = __ldg(&M[0]) * px + __ldg(&M[1]) * py + __ldg(&M[2])  * pz + __ldg(&M[3]);
    const float p1 = __ldg(&M[4]) * px + __ldg(&M[5]) * py + __ldg(&M[6])  * pz + __ldg(&M[7]);
    const float p2 = __ldg(&M[8]) * px + __ldg(&M[9]) * py + __ldg(&M[10]) * pz + __ldg(&M[11]);

    const float z     = fmaxf(p2, 1e-5f);
    const float x_pix = p0 / z;
    const float y_pix = p1 / z;

    const float padH = (float)__ldg(&pad_shape[(size_t)b * 2 + 0]);
    const float padW = (float)__ldg(&pad_shape[(size_t)b * 2 + 1]);

    const float gx = x_pix / padW * 2.0f - 1.0f;
    const float gy = y_pix / padH * 2.0f - 1.0f;
    const float ix = (gx + 1.0f) * 0.5f * (float)(WF - 1);
    const float iy = (gy + 1.0f) * 0.5f * (float)(HF - 1);

    const float ix0f = floorf(ix);
    const float iy0f = floorf(iy);
    const float wx1 = ix - ix0f, wx0 = 1.0f - wx1;
    const float wy1 = iy - iy0f, wy0 = 1.0f - wy1;

    const int ix0 = (int)ix0f, iy0 = (int)iy0f;
    const int ix1 = ix0 + 1,   iy1 = iy0 + 1;

    const bool vx0 = (ix0 >= 0) & (ix0 < WF);
    const bool vx1 = (ix1 >= 0) & (ix1 < WF);
    const bool vy0 = (iy0 >= 0) & (iy0 < HF);
    const bool vy1 = (iy1 >= 0) & (iy1 < HF);

    const float w00 = (vy0 & vx0) ? (wy0 * wx0) : 0.0f;
    const float w01 = (vy0 & vx1) ? (wy0 * wx1) : 0.0f;
    const float w10 = (vy1 & vx0) ? (wy1 * wx0) : 0.0f;
    const float w11 = (vy1 & vx1) ? (wy1 * wx1) : 0.0f;

    float4 a0 = make_float4(0.f, 0.f, 0.f, 0.f);
    float4 a1 = make_float4(0.f, 0.f, 0.f, 0.f);

    const float* base = g_imgT + (size_t)b * HW * CI;
    const int off0 = lane * 4;        // channels [4*lane, 4*lane+4)
    const int off1 = 128 + lane * 4;  // channels [128+4*lane, +4)

    corner_acc(base, iy0, ix0, w00, off0, off1, a0, a1);
    corner_acc(base, iy0, ix1, w01, off0, off1, a0, a1);
    corner_acc(base, iy1, ix0, w10, off0, off1, a0, a1);
    corner_acc(base, iy1, ix1, w11, off0, off1, a0, a1);

    // Output row: [64 voxel | 256 point] floats = 80 float4, 16B aligned.
    float4* orow = (float4*)(out + (size_t)n * OUTW);

    // voxel copy: 16 float4 by lanes 0..15 (dense 256B), streaming both ways
    if (lane < 16) {
        const float4* vrow = (const float4*)(voxel_feats + (size_t)n * CV);
        stcs4(&orow[lane], __ldcs(&vrow[lane]));
    }

    // point feats: dense 512B per store instruction, streaming
    stcs4(&orow[16 + lane],      a0);
    stcs4(&orow[16 + 32 + lane], a1);
}

// ---------------------------------------------------------------------------
extern "C" void kernel_launch(void* const* d_in, const int* in_sizes, int n_in,
                              void* d_out, int out_size) {
    const float* points_mean = (const float*)d_in[0];
    // d_in[1] = mask (unused by reference)
    const float* voxel_feats = (const float*)d_in[2];
    const int*   coors       = (const int*)  d_in[3];
    const float* img_feats   = (const float*)d_in[4];
    const float* lidar2img   = (const float*)d_in[5];
    const int*   pad_shape   = (const int*)  d_in[6];
    float*       out         = (float*)d_out;

    // Kernel A: transpose img_feats -> [B, H*W, C]
    dim3 tgrid(HW / 128, CI / 32, BATCH);   // (60, 8, 4)
    transpose_kernel<<<tgrid, 256>>>(img_feats);

    // Kernel B: one warp per point
    const int threads = 256;
    const int warps_per_block = threads / 32;
    const int blocks = (NPTS + warps_per_block - 1) / warps_per_block;
    sample_kernel<<<blocks, threads>>>(points_mean, voxel_feats, coors,
                                       lidar2img, pad_shape, out);
}

// round 4
// speedup vs baseline: 1.4462x; 1.3057x over previous
#include <cuda_runtime.h>
#include <cuda_bf16.h>
#include <cstdint>

// Problem constants (match reference)
#define NPTS 200000
#define BATCH 4
#define CV 64
#define CI 256
#define HF 48
#define WF 160
#define HW (HF * WF)          // 7680
#define OUTW (CV + CI)        // 320

// Scratch: img_feats transposed to [B, H, W, C] (channels contiguous).
// 4 * 7680 * 256 floats = 31.4 MB — L2-resident (L2 ~126 MB).
__device__ float g_imgT[(size_t)BATCH * HW * CI];
// Per-point precomputed gather metadata: element offsets into g_imgT (0 if
// the corner is invalid) and the 4 bilinear weights (0 if invalid).
__device__ int4   g_off[NPTS];
__device__ float4 g_w[NPTS];

// ---------------------------------------------------------------------------
// Kernel A: [B, C, H*W] -> [B, H*W, C] transpose, float4 on BOTH global sides.
// Tile: 32 channels x 128 positions. Block: 256 threads. Grid: (60, 8, 4).
// ---------------------------------------------------------------------------
__global__ __launch_bounds__(256)
void transpose_kernel(const float* __restrict__ img) {
    __shared__ float tile[32][129];
    const int b  = blockIdx.z;
    const int p0 = blockIdx.x * 128;
    const int c0 = blockIdx.y * 32;
    const int t  = threadIdx.x;

    const float* src = img    + (size_t)b * CI * HW;
    float*       dst = g_imgT + (size_t)b * HW * CI;

    #pragma unroll
    for (int r = 0; r < 4; r++) {
        const int linear = r * 256 + t;
        const int c = linear >> 5;
        const int q = linear & 31;
        float4 v = *(const float4*)(src + (size_t)(c0 + c) * HW + p0 + q * 4);
        tile[c][q * 4 + 0] = v.x;
        tile[c][q * 4 + 1] = v.y;
        tile[c][q * 4 + 2] = v.z;
        tile[c][q * 4 + 3] = v.w;
    }
    __syncthreads();

    #pragma unroll
    for (int r = 0; r < 4; r++) {
        const int linear = r * 256 + t;
        const int p  = linear >> 3;
        const int cq = linear & 7;
        float4 v;
        v.x = tile[cq * 4 + 0][p];
        v.y = tile[cq * 4 + 1][p];
        v.z = tile[cq * 4 + 2][p];
        v.w = tile[cq * 4 + 3][p];
        *(float4*)(dst + (size_t)(p0 + p) * CI + c0 + cq * 4) = v;
    }
}

// ---------------------------------------------------------------------------
// Kernel B: per-point projection metadata. ONE thread per point (the old
// version replicated this math across all 32 lanes of a warp).
// ---------------------------------------------------------------------------
__global__ __launch_bounds__(256)
void meta_kernel(const float* __restrict__ points_mean,
                 const int*   __restrict__ coors,
                 const float* __restrict__ lidar2img,
                 const int*   __restrict__ pad_shape) {
    const int n = blockIdx.x * blockDim.x + threadIdx.x;
    if (n >= NPTS) return;

    const int b = __ldg(&coors[(size_t)n * 4]);

    const float px = __ldg(&points_mean[(size_t)n * 3 + 0]);
    const float py = __ldg(&points_mean[(size_t)n * 3 + 1]);
    const float pz = __ldg(&points_mean[(size_t)n * 3 + 2]);

    const float* M = lidar2img + (size_t)b * 16;
    const float p0 = __ldg(&M[0]) * px + __ldg(&M[1]) * py + __ldg(&M[2])  * pz + __ldg(&M[3]);
    const float p1 = __ldg(&M[4]) * px + __ldg(&M[5]) * py + __ldg(&M[6])  * pz + __ldg(&M[7]);
    const float p2 = __ldg(&M[8]) * px + __ldg(&M[9]) * py + __ldg(&M[10]) * pz + __ldg(&M[11]);

    const float z     = fmaxf(p2, 1e-5f);
    const float x_pix = p0 / z;
    const float y_pix = p1 / z;

    const float padH = (float)__ldg(&pad_shape[(size_t)b * 2 + 0]);
    const float padW = (float)__ldg(&pad_shape[(size_t)b * 2 + 1]);

    const float gx = x_pix / padW * 2.0f - 1.0f;
    const float gy = y_pix / padH * 2.0f - 1.0f;
    const float ix = (gx + 1.0f) * 0.5f * (float)(WF - 1);
    const float iy = (gy + 1.0f) * 0.5f * (float)(HF - 1);

    const float ix0f = floorf(ix);
    const float iy0f = floorf(iy);
    const float wx1 = ix - ix0f, wx0 = 1.0f - wx1;
    const float wy1 = iy - iy0f, wy0 = 1.0f - wy1;

    const int ix0 = (int)ix0f, iy0 = (int)iy0f;
    const int ix1 = ix0 + 1,   iy1 = iy0 + 1;

    const bool vx0 = (ix0 >= 0) & (ix0 < WF);
    const bool vx1 = (ix1 >= 0) & (ix1 < WF);
    const bool vy0 = (iy0 >= 0) & (iy0 < HF);
    const bool vy1 = (iy1 >= 0) & (iy1 < HF);

    const float w00 = (vy0 & vx0) ? (wy0 * wx0) : 0.0f;
    const float w01 = (vy0 & vx1) ? (wy0 * wx1) : 0.0f;
    const float w10 = (vy1 & vx0) ? (wy1 * wx0) : 0.0f;
    const float w11 = (vy1 & vx1) ? (wy1 * wx1) : 0.0f;

    const int bbase = b * HW * CI;   // < 2^23 * 256 fits in int
    int4 off;
    off.x = (w00 != 0.0f) ? bbase + (iy0 * WF + ix0) * CI : 0;
    off.y = (w01 != 0.0f) ? bbase + (iy0 * WF + ix1) * CI : 0;
    off.z = (w10 != 0.0f) ? bbase + (iy1 * WF + ix0) * CI : 0;
    off.w = (w11 != 0.0f) ? bbase + (iy1 * WF + ix1) * CI : 0;

    g_off[n] = off;
    g_w[n]   = make_float4(w00, w01, w10, w11);
}

// corner accumulate; off is lane-uniform element offset into g_imgT
__device__ __forceinline__ void corner_acc(int off, float w,
                                           int off0, int off1,
                                           float4& a0, float4& a1) {
    if (w != 0.0f) {
        const float* row = g_imgT + off;
        float4 v0 = *(const float4*)(row + off0);
        float4 v1 = *(const float4*)(row + off1);
        a0.x += w * v0.x; a0.y += w * v0.y; a0.z += w * v0.z; a0.w += w * v0.w;
        a1.x += w * v1.x; a1.y += w * v1.y; a1.z += w * v1.z; a1.w += w * v1.w;
    }
}

// ---------------------------------------------------------------------------
// Kernel C: gather + write. One warp per 2 points (unrolled -> 2x MLP).
// Lane owns channels [4*lane,+4) and [128+4*lane,+4): all LDG.128/STG.128
// dense 512 B per warp. Meta loads are lane-uniform (broadcast). Output
// written with streaming stores to keep g_imgT L2-resident.
// ---------------------------------------------------------------------------
__global__ __launch_bounds__(256)
void gather_kernel(const float* __restrict__ voxel_feats,
                   float*       __restrict__ out) {
    const int gwarp = (blockIdx.x * blockDim.x + threadIdx.x) >> 5;
    const int lane  = threadIdx.x & 31;
    const int base  = gwarp * 2;
    if (base >= NPTS) return;

    const int off0 = lane * 4;
    const int off1 = 128 + lane * 4;

    #pragma unroll
    for (int i = 0; i < 2; i++) {
        const int n = base + i;     // NPTS even -> base+1 < NPTS always

        const int4   off = __ldg(&g_off[n]);   // lane-uniform broadcast
        const float4 w   = __ldg(&g_w[n]);

        float4 a0 = make_float4(0.f, 0.f, 0.f, 0.f);
        float4 a1 = make_float4(0.f, 0.f, 0.f, 0.f);

        corner_acc(off.x, w.x, off0, off1, a0, a1);
        corner_acc(off.y, w.y, off0, off1, a0, a1);
        corner_acc(off.z, w.z, off0, off1, a0, a1);
        corner_acc(off.w, w.w, off0, off1, a0, a1);

        float4* orow = (float4*)(out + (size_t)n * OUTW);

        if (lane < 16) {
            const float4* vrow = (const float4*)(voxel_feats + (size_t)n * CV);
            __stcs(&orow[lane], __ldcs(&vrow[lane]));
        }
        __stcs(&orow[16 + lane],      a0);
        __stcs(&orow[16 + 32 + lane], a1);
    }
}

// ---------------------------------------------------------------------------
extern "C" void kernel_launch(void* const* d_in, const int* in_sizes, int n_in,
                              void* d_out, int out_size) {
    const float* points_mean = (const float*)d_in[0];
    // d_in[1] = mask (unused by reference)
    const float* voxel_feats = (const float*)d_in[2];
    const int*   coors       = (const int*)  d_in[3];
    const float* img_feats   = (const float*)d_in[4];
    const float* lidar2img   = (const float*)d_in[5];
    const int*   pad_shape   = (const int*)  d_in[6];
    float*       out         = (float*)d_out;

    // A: transpose img_feats -> [B, H*W, C]
    dim3 tgrid(HW / 128, CI / 32, BATCH);   // (60, 8, 4)
    transpose_kernel<<<tgrid, 256>>>(img_feats);

    // B: per-point projection metadata (1 thread/point)
    meta_kernel<<<(NPTS + 255) / 256, 256>>>(points_mean, coors,
                                             lidar2img, pad_shape);

    // C: gather + write (1 warp / 2 points)
    const int warps = (NPTS + 1) / 2;               // 100000
    const int blocks = (warps * 32 + 255) / 256;    // 12500
    gather_kernel<<<blocks, 256>>>(voxel_feats, out);
}

// round 5
// speedup vs baseline: 1.4632x; 1.0118x over previous
#include <cuda_runtime.h>
#include <cuda_bf16.h>
#include <cstdint>

// Problem constants (match reference)
#define NPTS 200000
#define BATCH 4
#define CV 64
#define CI 256
#define HF 48
#define WF 160
#define HW (HF * WF)          // 7680
#define OUTW (CV + CI)        // 320

#define TR_BLOCKS 1920        // 60 * 8 * 4 transpose tiles
#define META_BLOCKS ((NPTS + 255) / 256)   // 782

// Scratch: img_feats transposed to [B, H, W, C] (channels contiguous).
// 31.4 MB — L2-resident (L2 ~126 MB).
__device__ float g_imgT[(size_t)BATCH * HW * CI];
// Per-point gather metadata: corner element offsets into g_imgT (0 if
// invalid) and the 4 bilinear weights (0 if invalid).
__device__ int4   g_off[NPTS];
__device__ float4 g_w[NPTS];

// ---------------------------------------------------------------------------
// Transpose tile body: [B, C, H*W] -> [B, H*W, C], float4 both global sides.
// Tile: 32 channels x 128 positions, 256 threads.
// ---------------------------------------------------------------------------
__device__ __forceinline__ void transpose_tile(const float* __restrict__ img,
                                               int tileId, int t) {
    __shared__ float tile[32][129];
    const int px = tileId % 60;          // position tile index
    const int cy = (tileId / 60) % 8;    // channel tile index
    const int b  = tileId / 480;         // batch
    const int p0 = px * 128;
    const int c0 = cy * 32;

    const float* src = img    + (size_t)b * CI * HW;
    float*       dst = g_imgT + (size_t)b * HW * CI;

    // Batch all 4 global loads first (max MLP), then store to smem.
    float4 v[4];
    int cc[4], qq[4];
    #pragma unroll
    for (int r = 0; r < 4; r++) {
        const int linear = r * 256 + t;
        cc[r] = linear >> 5;
        qq[r] = linear & 31;
        v[r] = *(const float4*)(src + (size_t)(c0 + cc[r]) * HW + p0 + qq[r] * 4);
    }
    #pragma unroll
    for (int r = 0; r < 4; r++) {
        tile[cc[r]][qq[r] * 4 + 0] = v[r].x;
        tile[cc[r]][qq[r] * 4 + 1] = v[r].y;
        tile[cc[r]][qq[r] * 4 + 2] = v[r].z;
        tile[cc[r]][qq[r] * 4 + 3] = v[r].w;
    }
    __syncthreads();

    #pragma unroll
    for (int r = 0; r < 4; r++) {
        const int linear = r * 256 + t;
        const int p  = linear >> 3;
        const int cq = linear & 7;
        float4 o;
        o.x = tile[cq * 4 + 0][p];
        o.y = tile[cq * 4 + 1][p];
        o.z = tile[cq * 4 + 2][p];
        o.w = tile[cq * 4 + 3][p];
        *(float4*)(dst + (size_t)(p0 + p) * CI + c0 + cq * 4) = o;
    }
}

// ---------------------------------------------------------------------------
// Meta body: per-point projection, ONE thread per point.
// ---------------------------------------------------------------------------
__device__ __forceinline__ void meta_point(const float* __restrict__ points_mean,
                                           const int*   __restrict__ coors,
                                           const float* __restrict__ lidar2img,
                                           const int*   __restrict__ pad_shape,
                                           int n) {
    const int b = __ldg(&coors[(size_t)n * 4]);

    const float px = __ldg(&points_mean[(size_t)n * 3 + 0]);
    const float py = __ldg(&points_mean[(size_t)n * 3 + 1]);
    const float pz = __ldg(&points_mean[(size_t)n * 3 + 2]);

    const float* M = lidar2img + (size_t)b * 16;
    const float p0 = __ldg(&M[0]) * px + __ldg(&M[1]) * py + __ldg(&M[2])  * pz + __ldg(&M[3]);
    const float p1 = __ldg(&M[4]) * px + __ldg(&M[5]) * py + __ldg(&M[6])  * pz + __ldg(&M[7]);
    const float p2 = __ldg(&M[8]) * px + __ldg(&M[9]) * py + __ldg(&M[10]) * pz + __ldg(&M[11]);

    const float z     = fmaxf(p2, 1e-5f);
    const float x_pix = p0 / z;
    const float y_pix = p1 / z;

    const float padH = (float)__ldg(&pad_shape[(size_t)b * 2 + 0]);
    const float padW = (float)__ldg(&pad_shape[(size_t)b * 2 + 1]);

    const float gx = x_pix / padW * 2.0f - 1.0f;
    const float gy = y_pix / padH * 2.0f - 1.0f;
    const float ix = (gx + 1.0f) * 0.5f * (float)(WF - 1);
    const float iy = (gy + 1.0f) * 0.5f * (float)(HF - 1);

    const float ix0f = floorf(ix);
    const float iy0f = floorf(iy);
    const float wx1 = ix - ix0f, wx0 = 1.0f - wx1;
    const float wy1 = iy - iy0f, wy0 = 1.0f - wy1;

    const int ix0 = (int)ix0f, iy0 = (int)iy0f;
    const int ix1 = ix0 + 1,   iy1 = iy0 + 1;

    const bool vx0 = (ix0 >= 0) & (ix0 < WF);
    const bool vx1 = (ix1 >= 0) & (ix1 < WF);
    const bool vy0 = (iy0 >= 0) & (iy0 < HF);
    const bool vy1 = (iy1 >= 0) & (iy1 < HF);

    const float w00 = (vy0 & vx0) ? (wy0 * wx0) : 0.0f;
    const float w01 = (vy0 & vx1) ? (wy0 * wx1) : 0.0f;
    const float w10 = (vy1 & vx0) ? (wy1 * wx0) : 0.0f;
    const float w11 = (vy1 & vx1) ? (wy1 * wx1) : 0.0f;

    const int bbase = b * HW * CI;
    int4 off;
    off.x = (w00 != 0.0f) ? bbase + (iy0 * WF + ix0) * CI : 0;
    off.y = (w01 != 0.0f) ? bbase + (iy0 * WF + ix1) * CI : 0;
    off.z = (w10 != 0.0f) ? bbase + (iy1 * WF + ix0) * CI : 0;
    off.w = (w11 != 0.0f) ? bbase + (iy1 * WF + ix1) * CI : 0;

    g_off[n] = off;
    g_w[n]   = make_float4(w00, w01, w10, w11);
}

// ---------------------------------------------------------------------------
// Kernel A: fused transpose + meta. Blocks [0, TR_BLOCKS) do transpose tiles;
// blocks [TR_BLOCKS, TR_BLOCKS+META_BLOCKS) do per-point projection math.
// Independent work co-scheduled in one wave instead of two serial launches.
// ---------------------------------------------------------------------------
__global__ __launch_bounds__(256)
void prep_kernel(const float* __restrict__ img,
                 const float* __restrict__ points_mean,
                 const int*   __restrict__ coors,
                 const float* __restrict__ lidar2img,
                 const int*   __restrict__ pad_shape) {
    if (blockIdx.x < TR_BLOCKS) {
        transpose_tile(img, blockIdx.x, threadIdx.x);
    } else {
        const int n = (blockIdx.x - TR_BLOCKS) * 256 + threadIdx.x;
        if (n < NPTS)
            meta_point(points_mean, coors, lidar2img, pad_shape, n);
    }
}

// corner accumulate; off is lane-uniform element offset into g_imgT
__device__ __forceinline__ void corner_acc(int off, float w,
                                           int off0, int off1,
                                           float4& a0, float4& a1) {
    if (w != 0.0f) {
        const float* row = g_imgT + off;
        float4 v0 = *(const float4*)(row + off0);
        float4 v1 = *(const float4*)(row + off1);
        a0.x += w * v0.x; a0.y += w * v0.y; a0.z += w * v0.z; a0.w += w * v0.w;
        a1.x += w * v1.x; a1.y += w * v1.y; a1.z += w * v1.z; a1.w += w * v1.w;
    }
}

// ---------------------------------------------------------------------------
// Kernel B: gather + write. One warp per 2 points (unrolled -> 2x MLP).
// Lane owns channels [4*lane,+4) and [128+4*lane,+4): all LDG.128/STG.128
// dense 512 B per warp. Meta loads lane-uniform (broadcast). Output streaming.
// ---------------------------------------------------------------------------
__global__ __launch_bounds__(256)
void gather_kernel(const float* __restrict__ voxel_feats,
                   float*       __restrict__ out) {
    const int gwarp = (blockIdx.x * blockDim.x + threadIdx.x) >> 5;
    const int lane  = threadIdx.x & 31;
    const int base  = gwarp * 2;
    if (base >= NPTS) return;

    const int off0 = lane * 4;
    const int off1 = 128 + lane * 4;

    #pragma unroll
    for (int i = 0; i < 2; i++) {
        const int n = base + i;     // NPTS even -> in bounds

        const int4   off = __ldg(&g_off[n]);
        const float4 w   = __ldg(&g_w[n]);

        float4 a0 = make_float4(0.f, 0.f, 0.f, 0.f);
        float4 a1 = make_float4(0.f, 0.f, 0.f, 0.f);

        corner_acc(off.x, w.x, off0, off1, a0, a1);
        corner_acc(off.y, w.y, off0, off1, a0, a1);
        corner_acc(off.z, w.z, off0, off1, a0, a1);
        corner_acc(off.w, w.w, off0, off1, a0, a1);

        float4* orow = (float4*)(out + (size_t)n * OUTW);

        if (lane < 16) {
            const float4* vrow = (const float4*)(voxel_feats + (size_t)n * CV);
            __stcs(&orow[lane], __ldcs(&vrow[lane]));
        }
        __stcs(&orow[16 + lane],      a0);
        __stcs(&orow[16 + 32 + lane], a1);
    }
}

// ---------------------------------------------------------------------------
extern "C" void kernel_launch(void* const* d_in, const int* in_sizes, int n_in,
                              void* d_out, int out_size) {
    const float* points_mean = (const float*)d_in[0];
    // d_in[1] = mask (unused by reference)
    const float* voxel_feats = (const float*)d_in[2];
    const int*   coors       = (const int*)  d_in[3];
    const float* img_feats   = (const float*)d_in[4];
    const float* lidar2img   = (const float*)d_in[5];
    const int*   pad_shape   = (const int*)  d_in[6];
    float*       out         = (float*)d_out;

    // A: fused transpose + projection meta (co-scheduled)
    prep_kernel<<<TR_BLOCKS + META_BLOCKS, 256>>>(img_feats, points_mean,
                                                  coors, lidar2img, pad_shape);

    // B: gather + write (1 warp / 2 points)
    const int warps = (NPTS + 1) / 2;               // 100000
    const int blocks = (warps * 32 + 255) / 256;    // 12500
    gather_kernel<<<blocks, 256>>>(voxel_feats, out);
}

// round 6
// speedup vs baseline: 1.4821x; 1.0129x over previous
#include <cuda_runtime.h>
#include <cuda_bf16.h>
#include <cstdint>

// Problem constants (match reference)
#define NPTS 200000
#define BATCH 4
#define CV 64
#define CI 256
#define HF 48
#define WF 160
#define HW (HF * WF)          // 7680
#define OUTW (CV + CI)        // 320

#define TR_BLOCKS 1920        // 60 * 8 * 4 transpose tiles
#define META_BLOCKS ((NPTS + 255) / 256)   // 782
#define PTS_PER_BLOCK 16      // gather: 8 warps x 2 points

// Scratch: img_feats transposed to [B, H, W, C] (channels contiguous).
// 31.4 MB — L2-resident (L2 ~126 MB).
__device__ float g_imgT[(size_t)BATCH * HW * CI];
// Per-point gather metadata: corner element offsets into g_imgT (0 if
// invalid) and the 4 bilinear weights (0 if invalid).
__device__ int4   g_off[NPTS];
__device__ float4 g_w[NPTS];

// ---------------------------------------------------------------------------
// Transpose tile body: [B, C, H*W] -> [B, H*W, C], float4 both global sides.
// ---------------------------------------------------------------------------
__device__ __forceinline__ void transpose_tile(const float* __restrict__ img,
                                               int tileId, int t) {
    __shared__ float tile[32][129];
    const int px = tileId % 60;
    const int cy = (tileId / 60) % 8;
    const int b  = tileId / 480;
    const int p0 = px * 128;
    const int c0 = cy * 32;

    const float* src = img    + (size_t)b * CI * HW;
    float*       dst = g_imgT + (size_t)b * HW * CI;

    float4 v[4];
    int cc[4], qq[4];
    #pragma unroll
    for (int r = 0; r < 4; r++) {
        const int linear = r * 256 + t;
        cc[r] = linear >> 5;
        qq[r] = linear & 31;
        v[r] = *(const float4*)(src + (size_t)(c0 + cc[r]) * HW + p0 + qq[r] * 4);
    }
    #pragma unroll
    for (int r = 0; r < 4; r++) {
        tile[cc[r]][qq[r] * 4 + 0] = v[r].x;
        tile[cc[r]][qq[r] * 4 + 1] = v[r].y;
        tile[cc[r]][qq[r] * 4 + 2] = v[r].z;
        tile[cc[r]][qq[r] * 4 + 3] = v[r].w;
    }
    __syncthreads();

    #pragma unroll
    for (int r = 0; r < 4; r++) {
        const int linear = r * 256 + t;
        const int p  = linear >> 3;
        const int cq = linear & 7;
        float4 o;
        o.x = tile[cq * 4 + 0][p];
        o.y = tile[cq * 4 + 1][p];
        o.z = tile[cq * 4 + 2][p];
        o.w = tile[cq * 4 + 3][p];
        *(float4*)(dst + (size_t)(p0 + p) * CI + c0 + cq * 4) = o;
    }
}

// ---------------------------------------------------------------------------
// Meta body: per-point projection, ONE thread per point.
// ---------------------------------------------------------------------------
__device__ __forceinline__ void meta_point(const float* __restrict__ points_mean,
                                           const int*   __restrict__ coors,
                                           const float* __restrict__ lidar2img,
                                           const int*   __restrict__ pad_shape,
                                           int n) {
    const int b = __ldg(&coors[(size_t)n * 4]);

    const float px = __ldg(&points_mean[(size_t)n * 3 + 0]);
    const float py = __ldg(&points_mean[(size_t)n * 3 + 1]);
    const float pz = __ldg(&points_mean[(size_t)n * 3 + 2]);

    const float* M = lidar2img + (size_t)b * 16;
    const float p0 = __ldg(&M[0]) * px + __ldg(&M[1]) * py + __ldg(&M[2])  * pz + __ldg(&M[3]);
    const float p1 = __ldg(&M[4]) * px + __ldg(&M[5]) * py + __ldg(&M[6])  * pz + __ldg(&M[7]);
    const float p2 = __ldg(&M[8]) * px + __ldg(&M[9]) * py + __ldg(&M[10]) * pz + __ldg(&M[11]);

    const float z     = fmaxf(p2, 1e-5f);
    const float x_pix = p0 / z;
    const float y_pix = p1 / z;

    const float padH = (float)__ldg(&pad_shape[(size_t)b * 2 + 0]);
    const float padW = (float)__ldg(&pad_shape[(size_t)b * 2 + 1]);

    const float gx = x_pix / padW * 2.0f - 1.0f;
    const float gy = y_pix / padH * 2.0f - 1.0f;
    const float ix = (gx + 1.0f) * 0.5f * (float)(WF - 1);
    const float iy = (gy + 1.0f) * 0.5f * (float)(HF - 1);

    const float ix0f = floorf(ix);
    const float iy0f = floorf(iy);
    const float wx1 = ix - ix0f, wx0 = 1.0f - wx1;
    const float wy1 = iy - iy0f, wy0 = 1.0f - wy1;

    const int ix0 = (int)ix0f, iy0 = (int)iy0f;
    const int ix1 = ix0 + 1,   iy1 = iy0 + 1;

    const bool vx0 = (ix0 >= 0) & (ix0 < WF);
    const bool vx1 = (ix1 >= 0) & (ix1 < WF);
    const bool vy0 = (iy0 >= 0) & (iy0 < HF);
    const bool vy1 = (iy1 >= 0) & (iy1 < HF);

    const float w00 = (vy0 & vx0) ? (wy0 * wx0) : 0.0f;
    const float w01 = (vy0 & vx1) ? (wy0 * wx1) : 0.0f;
    const float w10 = (vy1 & vx0) ? (wy1 * wx0) : 0.0f;
    const float w11 = (vy1 & vx1) ? (wy1 * wx1) : 0.0f;

    const int bbase = b * HW * CI;
    int4 off;
    off.x = (w00 != 0.0f) ? bbase + (iy0 * WF + ix0) * CI : 0;
    off.y = (w01 != 0.0f) ? bbase + (iy0 * WF + ix1) * CI : 0;
    off.z = (w10 != 0.0f) ? bbase + (iy1 * WF + ix0) * CI : 0;
    off.w = (w11 != 0.0f) ? bbase + (iy1 * WF + ix1) * CI : 0;

    g_off[n] = off;
    g_w[n]   = make_float4(w00, w01, w10, w11);
}

// ---------------------------------------------------------------------------
// Kernel A: fused transpose + meta (independent work co-scheduled).
// ---------------------------------------------------------------------------
__global__ __launch_bounds__(256)
void prep_kernel(const float* __restrict__ img,
                 const float* __restrict__ points_mean,
                 const int*   __restrict__ coors,
                 const float* __restrict__ lidar2img,
                 const int*   __restrict__ pad_shape) {
    if (blockIdx.x < TR_BLOCKS) {
        transpose_tile(img, blockIdx.x, threadIdx.x);
    } else {
        const int n = (blockIdx.x - TR_BLOCKS) * 256 + threadIdx.x;
        if (n < NPTS)
            meta_point(points_mean, coors, lidar2img, pad_shape, n);
    }
}

// corner accumulate; off is lane-uniform element offset into g_imgT
__device__ __forceinline__ void corner_acc(int off, float w,
                                           int off0, int off1,
                                           float4& a0, float4& a1) {
    if (w != 0.0f) {
        const float* row = g_imgT + off;
        float4 v0 = *(const float4*)(row + off0);
        float4 v1 = *(const float4*)(row + off1);
        a0.x += w * v0.x; a0.y += w * v0.y; a0.z += w * v0.z; a0.w += w * v0.w;
        a1.x += w * v1.x; a1.y += w * v1.y; a1.z += w * v1.z; a1.w += w * v1.w;
    }
}

// ---------------------------------------------------------------------------
// Kernel B: gather + write. Block (8 warps) owns 16 consecutive points.
// Meta for all 16 points batch-loaded into smem up front (32 parallel LDGs)
// -> per-point meta is a 29-cycle LDS broadcast, off the critical path.
// Warp handles 2 points (unrolled). All LDG.128/STG.128 dense 512 B.
// ---------------------------------------------------------------------------
__global__ __launch_bounds__(256)
void gather_kernel(const float* __restrict__ voxel_feats,
                   float*       __restrict__ out) {
    __shared__ int4   s_off[PTS_PER_BLOCK];
    __shared__ float4 s_w[PTS_PER_BLOCK];

    const int t    = threadIdx.x;
    const int base = blockIdx.x * PTS_PER_BLOCK;

    if (t < PTS_PER_BLOCK) {
        s_off[t] = __ldg(&g_off[base + t]);
    } else if (t < 2 * PTS_PER_BLOCK) {
        s_w[t - PTS_PER_BLOCK] = __ldg(&g_w[base + t - PTS_PER_BLOCK]);
    }
    __syncthreads();

    const int warp = t >> 5;   // 0..7
    const int lane = t & 31;
    const int off0 = lane * 4;
    const int off1 = 128 + lane * 4;

    #pragma unroll
    for (int i = 0; i < 2; i++) {
        const int li = warp * 2 + i;   // 0..15
        const int n  = base + li;      // NPTS % 16 == 0 -> in bounds

        const int4   off = s_off[li];  // LDS broadcast
        const float4 w   = s_w[li];

        // independent voxel load issued before the gather chain
        float4 vx = make_float4(0.f, 0.f, 0.f, 0.f);
        if (lane < 16) {
            const float4* vrow = (const float4*)(voxel_feats + (size_t)n * CV);
            vx = __ldcs(&vrow[lane]);
        }

        float4 a0 = make_float4(0.f, 0.f, 0.f, 0.f);
        float4 a1 = make_float4(0.f, 0.f, 0.f, 0.f);

        corner_acc(off.x, w.x, off0, off1, a0, a1);
        corner_acc(off.y, w.y, off0, off1, a0, a1);
        corner_acc(off.z, w.z, off0, off1, a0, a1);
        corner_acc(off.w, w.w, off0, off1, a0, a1);

        float4* orow = (float4*)(out + (size_t)n * OUTW);
        if (lane < 16) __stcs(&orow[lane], vx);
        __stcs(&orow[16 + lane],      a0);
        __stcs(&orow[16 + 32 + lane], a1);
    }
}

// ---------------------------------------------------------------------------
extern "C" void kernel_launch(void* const* d_in, const int* in_sizes, int n_in,
                              void* d_out, int out_size) {
    const float* points_mean = (const float*)d_in[0];
    // d_in[1] = mask (unused by reference)
    const float* voxel_feats = (const float*)d_in[2];
    const int*   coors       = (const int*)  d_in[3];
    const float* img_feats   = (const float*)d_in[4];
    const float* lidar2img   = (const float*)d_in[5];
    const int*   pad_shape   = (const int*)  d_in[6];
    float*       out         = (float*)d_out;

    // A: fused transpose + projection meta
    prep_kernel<<<TR_BLOCKS + META_BLOCKS, 256>>>(img_feats, points_mean,
                                                  coors, lidar2img, pad_shape);

    // B: gather + write (block = 16 points)
    gather_kernel<<<NPTS / PTS_PER_BLOCK, 256>>>(voxel_feats, out);
}